// round 3
// baseline (speedup 1.0000x reference)
#include <cuda_runtime.h>
#include <cstdint>

// Shapes (fixed): B=128, CIN=16, COUT=16, F=512, N=32, K=2
#define BB   128
#define CI   16
#define CO   16
#define FF   512
#define NN   32
#define NTILES ((BB * FF) / 16)     // 4096 tiles of 16 (b,f)-rows
#define GRID   304                  // 2 persistent blocks per SM (152 SMs)

// ---------------- smem layout (dynamic) ----------------
// sW4   : float4[4096]  = 64 KB   Weff, [i][c][npair] = (n0k0,n1k0,n0k1,n1k1)
// sX    : float [2][8][16][32] = 32 KB  ring: [buf][i_local][row][n]
// sBias : float2[256]   = 2 KB    [c][npair] = (beff(n0,c), beff(n1,c))
// mbar  : uint64[2]
#define SW_OFF    0
#define SX_OFF    65536
#define SB_OFF    (SX_OFF + 32768)
#define MB_OFF    (SB_OFF + 2048)
#define SMEM_BYTES (MB_OFF + 64)

__device__ __forceinline__ uint32_t smem_u32(const void* p) {
    uint32_t a;
    asm("{ .reg .u64 t; cvta.to.shared.u64 t, %1; cvt.u32.u64 %0, t; }" : "=r"(a) : "l"(p));
    return a;
}
__device__ __forceinline__ void ffma2(uint64_t& acc, uint64_t a, uint64_t b) {
    asm("fma.rn.f32x2 %0, %1, %2, %0;" : "+l"(acc) : "l"(a), "l"(b));
}
__device__ __forceinline__ float2 u2f2(uint64_t v) {
    float2 f;
    asm("mov.b64 {%0, %1}, %2;" : "=f"(f.x), "=f"(f.y) : "l"(v));
    return f;
}
__device__ __forceinline__ void mbar_init(uint32_t mbar, uint32_t cnt) {
    asm volatile("mbarrier.init.shared.b64 [%0], %1;" :: "r"(mbar), "r"(cnt) : "memory");
}
__device__ __forceinline__ void mbar_expect_tx(uint32_t mbar, uint32_t bytes) {
    asm volatile("mbarrier.arrive.expect_tx.shared.b64 _, [%0], %1;" :: "r"(mbar), "r"(bytes) : "memory");
}
__device__ __forceinline__ void mbar_wait(uint32_t mbar, uint32_t parity) {
    uint32_t done;
    asm volatile(
        "{\n\t.reg .pred p;\n\t"
        "mbarrier.try_wait.parity.acquire.cta.shared::cta.b64 p, [%1], %2;\n\t"
        "selp.b32 %0, 1, 0, p;\n\t}"
        : "=r"(done) : "r"(mbar), "r"(parity) : "memory");
    if (!done) {
        asm volatile(
            "{\n\t.reg .pred P1;\n\t"
            "W_%=:\n\t"
            "mbarrier.try_wait.parity.acquire.cta.shared::cta.b64 P1, [%0], %1, 0x989680;\n\t"
            "@P1 bra.uni D_%=;\n\t"
            "bra.uni W_%=;\n\t"
            "D_%=:\n\t}"
            :: "r"(mbar), "r"(parity) : "memory");
    }
}
__device__ __forceinline__ void bulk_g2s(uint32_t dst, const void* src, uint32_t bytes, uint32_t mbar) {
    asm volatile(
        "cp.async.bulk.shared::cta.global.mbarrier::complete_tx::bytes [%0], [%1], %2, [%3];"
        :: "r"(dst), "l"(src), "r"(bytes), "r"(mbar) : "memory");
}
__device__ __forceinline__ void fence_async() {
    asm volatile("fence.proxy.async.shared::cta;" ::: "memory");
}

__global__ __launch_bounds__(256, 2)
void fused_kernel(const float* __restrict__ x,
                  const float* __restrict__ W1, const float* __restrict__ b1,
                  const float* __restrict__ W2, const float* __restrict__ b2,
                  float* __restrict__ out)
{
    extern __shared__ char smem[];
    float4*  sW4   = (float4*)(smem + SW_OFF);
    float*   sX    = (float*) (smem + SX_OFF);
    float2*  sBias = (float2*)(smem + SB_OFF);
    const uint32_t smb   = smem_u32(smem);
    const uint32_t mbar0 = smb + MB_OFF;
    const uint32_t mbar1 = smb + MB_OFF + 8;

    const int tid = threadIdx.x;
    const int bx  = blockIdx.x;

    // number of tiles / stages this block owns (grid-stride)
    const int ntile = (NTILES - 1 - bx) / GRID + 1;
    const int G = 2 * ntile;

    if (tid == 0) { mbar_init(mbar0, 1); mbar_init(mbar1, 1); }
    __syncthreads();

    // ---- issue first two ring stages (tid 0) ----
    if (tid == 0) {
        fence_async();
#pragma unroll
        for (int g = 0; g < 2; ++g) {
            if (g < G) {
                const int tile = bx + (g >> 1) * GRID;
                const int b = tile >> 5;
                const int f = (tile & 31) * 16;
                const int i0 = (g & 1) * 8;
                uint32_t mb = (g & 1) ? mbar1 : mbar0;
                mbar_expect_tx(mb, 16384);
                uint32_t dst = smb + SX_OFF + (g & 1) * 16384;
#pragma unroll
                for (int il = 0; il < 8; ++il)
                    bulk_g2s(dst + il * 2048,
                             x + ((size_t)(b * CI + i0 + il) * FF + f) * NN,
                             2048, mb);
            }
        }
    }

    // ---- prologue: fold W1*W2 -> sW4, bias -> sBias (overlaps the copies) ----
    {
        const int c  = tid >> 4;
        const int np = tid & 15;
        const int n0 = 2 * np, n1 = n0 + 1;
        float w2a[16], w2b[16];
#pragma unroll
        for (int o = 0; o < CO; ++o) {
            w2a[o] = __ldg(W2 + (n0 * CO + o) * CO + c);
            w2b[o] = __ldg(W2 + (n1 * CO + o) * CO + c);
        }
        float ba = __ldg(b2 + n0 * CO + c);
        float bb = __ldg(b2 + n1 * CO + c);
#pragma unroll
        for (int o = 0; o < CO; ++o) {
            ba = fmaf(__ldg(b1 + n0 * CO + o), w2a[o], ba);
            bb = fmaf(__ldg(b1 + n1 * CO + o), w2b[o], bb);
        }
        sBias[c * 16 + np] = make_float2(ba, bb);
#pragma unroll
        for (int i = 0; i < CI; ++i) {
            float s0x = 0.f, s0y = 0.f, s1x = 0.f, s1y = 0.f;
            const float2* wa = (const float2*)(W1 + ((size_t)(n0 * CI + i) * CO) * 2);
            const float2* wb = (const float2*)(W1 + ((size_t)(n1 * CI + i) * CO) * 2);
#pragma unroll
            for (int o = 0; o < CO; ++o) {
                float2 a = __ldg(wa + o);
                float2 bq = __ldg(wb + o);
                s0x = fmaf(a.x,  w2a[o], s0x);   // n0,k0
                s0y = fmaf(a.y,  w2a[o], s0y);   // n0,k1
                s1x = fmaf(bq.x, w2b[o], s1x);   // n1,k0
                s1y = fmaf(bq.y, w2b[o], s1y);   // n1,k1
            }
            sW4[(i * CO + c) * 16 + np] = make_float4(s0x, s1x, s0y, s1y);
        }
    }
    __syncthreads();

    // ---- per-warp layout ----
    const int lane = tid & 31;
    const int np   = lane & 15;          // n-pair (n0=2np, n1=2np+1)
    const int s    = lane >> 4;          // row slot within warp
    const int warp = tid >> 5;
    const int c0   = (warp & 3) * 4;     // 4 channels per warp
    const int gg   = warp >> 2;          // row half (rows gg*8 .. gg*8+7)

    uint64_t bias[4];
#pragma unroll
    for (int cc = 0; cc < 4; ++cc)
        bias[cc] = *(const uint64_t*)&sBias[(c0 + cc) * 16 + np];

    const ulonglong2* wp = (const ulonglong2*)sW4;
    float4* out4 = (float4*)out;

    uint64_t acc[4][4][2];   // [j(row)][cc][k]

    // ---- main pipelined loop over stages ----
    for (int g = 0; g < G; ++g) {
        const int buf  = g & 1;
        const int ph   = (g >> 1) & 1;
        const int tile = bx + (g >> 1) * GRID;
        const int b    = tile >> 5;
        const int f    = (tile & 31) * 16;

        mbar_wait(buf ? mbar1 : mbar0, ph);

        if (!(g & 1)) {
#pragma unroll
            for (int cc = 0; cc < 4; ++cc)
#pragma unroll
                for (int j = 0; j < 4; ++j) {
                    acc[j][cc][0] = bias[cc];
                    acc[j][cc][1] = bias[cc];
                }
        }

        // x base for this warp inside the stage buffer (floats)
        const float* xs = sX + buf * 4096 + (gg * 8 + s) * 32 + np * 2;
        const int ibase = (g & 1) * 8;

#pragma unroll
        for (int il = 0; il < 8; ++il) {
            uint64_t xv[4];
#pragma unroll
            for (int j = 0; j < 4; ++j)
                xv[j] = *(const uint64_t*)(xs + il * 512 + j * 64);
#pragma unroll
            for (int cc = 0; cc < 4; ++cc) {
                ulonglong2 w = wp[((ibase + il) * CO + c0 + cc) * 16 + np];
#pragma unroll
                for (int j = 0; j < 4; ++j) {
                    ffma2(acc[j][cc][0], xv[j], w.x);
                    ffma2(acc[j][cc][1], xv[j], w.y);
                }
            }
        }

        if (g & 1) {
            // out[b, c, f+row, 4np .. 4np+3] ; float4 units
            size_t obase = ((size_t)(b * CO + c0) * FF + f + gg * 8 + s) * 16 + np;
#pragma unroll
            for (int cc = 0; cc < 4; ++cc)
#pragma unroll
                for (int j = 0; j < 4; ++j) {
                    float2 p = u2f2(acc[j][cc][0]);   // (n0k0, n1k0)
                    float2 q = u2f2(acc[j][cc][1]);   // (n0k1, n1k1)
                    out4[obase + (size_t)cc * (FF * 16) + j * 32] =
                        make_float4(p.x, q.x, p.y, q.y);
                }
        }

        __syncthreads();   // all warps done with this buffer

        if (tid == 0 && g + 2 < G) {
            const int g2 = g + 2;
            const int t2 = bx + (g2 >> 1) * GRID;
            const int b2i = t2 >> 5;
            const int f2 = (t2 & 31) * 16;
            const int i0 = (g2 & 1) * 8;
            uint32_t mb = buf ? mbar1 : mbar0;
            fence_async();
            mbar_expect_tx(mb, 16384);
            uint32_t dst = smb + SX_OFF + buf * 16384;
#pragma unroll
            for (int il = 0; il < 8; ++il)
                bulk_g2s(dst + il * 2048,
                         x + ((size_t)(b2i * CI + i0 + il) * FF + f2) * NN,
                         2048, mb);
        }
    }
}

// ---------------------------------------------------------------------------
extern "C" void kernel_launch(void* const* d_in, const int* in_sizes, int n_in,
                              void* d_out, int out_size)
{
    const float* x  = (const float*)d_in[0];
    const float* W1 = (const float*)d_in[1];
    const float* b1 = (const float*)d_in[2];
    const float* W2 = (const float*)d_in[3];
    const float* b2 = (const float*)d_in[4];
    float* out = (float*)d_out;

    cudaFuncSetAttribute(fused_kernel, cudaFuncAttributeMaxDynamicSharedMemorySize,
                         SMEM_BYTES);
    fused_kernel<<<GRID, 256, SMEM_BYTES>>>(x, W1, b1, W2, b2, out);
}